// round 12
// baseline (speedup 1.0000x reference)
#include <cuda_runtime.h>
#include <cuda_fp16.h>
#include <cstdint>

#define NROW 200000
#define XDIM 480
#define NT32 6250          // 200000/32
#define GRID 152
#define NTHR 1024
#define VSTRIDE 304        // 152 CTAs * 2 halves

#define DINL __device__ __forceinline__

DINL unsigned su32(const void* p){ return (unsigned)__cvta_generic_to_shared(p); }

DINL void cpasync16(unsigned dst, const void* src){
  asm volatile("cp.async.ca.shared.global [%0], [%1], 16;" :: "r"(dst), "l"(src));
}
DINL void cpcommit(){ asm volatile("cp.async.commit_group;" ::: "memory"); }
DINL void cpwait0(){ asm volatile("cp.async.wait_group 0;" ::: "memory"); }
DINL void barh(int id){ asm volatile("bar.sync %0, 512;" :: "r"(id) : "memory"); }

DINL void ldmx4(unsigned &r0,unsigned &r1,unsigned &r2,unsigned &r3, unsigned a){
  asm volatile("ldmatrix.sync.aligned.m8n8.x4.shared.b16 {%0,%1,%2,%3}, [%4];"
    : "=r"(r0),"=r"(r1),"=r"(r2),"=r"(r3) : "r"(a));
}
DINL void ldmx4t(unsigned &r0,unsigned &r1,unsigned &r2,unsigned &r3, unsigned a){
  asm volatile("ldmatrix.sync.aligned.m8n8.x4.trans.shared.b16 {%0,%1,%2,%3}, [%4];"
    : "=r"(r0),"=r"(r1),"=r"(r2),"=r"(r3) : "r"(a));
}
DINL void ldmx2t(unsigned &r0,unsigned &r1, unsigned a){
  asm volatile("ldmatrix.sync.aligned.m8n8.x2.trans.shared.b16 {%0,%1}, [%2];"
    : "=r"(r0),"=r"(r1) : "r"(a));
}
DINL void mma16816(float* c, unsigned a0,unsigned a1,unsigned a2,unsigned a3,
                   unsigned b0,unsigned b1){
  asm volatile("mma.sync.aligned.m16n8k16.row.col.f32.f16.f16.f32 "
    "{%0,%1,%2,%3}, {%4,%5,%6,%7}, {%8,%9}, {%0,%1,%2,%3};"
    : "+f"(c[0]),"+f"(c[1]),"+f"(c[2]),"+f"(c[3])
    : "r"(a0),"r"(a1),"r"(a2),"r"(a3),"r"(b0),"r"(b1));
}
DINL float sigm(float v){ return 1.f/(1.f+__expf(-v)); }

DINL unsigned aaddr(unsigned base, int stride, int r0, int k0, int lane){
  int r = r0 + (lane & 15);
  int c = k0 + ((lane >> 4) << 3);
  return base + (unsigned)((r * stride + c) << 1);
}
DINL unsigned baddr(unsigned base, int stride, int k0, int c0, int lane){
  int r = k0 + (lane & 7) + (((lane >> 3) & 1) << 3);
  int c = c0 + ((lane >> 4) << 3);
  return base + (unsigned)((r * stride + c) << 1);
}
DINL unsigned b2addr(unsigned base, int stride, int k0, int c0, int lane){
  int r = k0 + (lane & 15);
  return base + (unsigned)((r * stride + c0) << 1);
}

// fp16 weights with 1/sqrt(fan_in) folded
__device__ __half WP0[128*256];
__device__ __half WQ0[256*128];
__device__ __half WP1[64*128];
__device__ __half WQ1[128*64];
__device__ __half WP2[32*64];
__device__ __half WQ2[64*32];

__global__ void k_prep(const float* __restrict__ p0, const float* __restrict__ p1,
                       const float* __restrict__ p2, const float* __restrict__ q0,
                       const float* __restrict__ q1, const float* __restrict__ q2){
  int t = blockIdx.x*blockDim.x + threadIdx.x, st = gridDim.x*blockDim.x;
  for (int i=t;i<128*256;i+=st) WP0[i] = __float2half(p0[i]*0.08838834764831845f);
  for (int i=t;i<64*128;i+=st)  WP1[i] = __float2half(p1[i]*0.125f);
  for (int i=t;i<32*64;i+=st)   WP2[i] = __float2half(p2[i]*0.17677669529663687f);
  for (int i=t;i<256*128;i+=st) WQ0[i] = __float2half(q0[i]*0.0625f);
  for (int i=t;i<128*64;i+=st)  WQ1[i] = __float2half(q1[i]*0.08838834764831845f);
  for (int i=t;i<64*32;i+=st)   WQ2[i] = __float2half(q2[i]*0.125f);
}

// ============================ l = 0 (round-10, unchanged) ============================
struct SL0 {
  float  nw[128], nb[128];
  __half wp[128][264];
  __half wq[256][136];
  struct HF { __half A[32][136]; __half H[32][264]; float xb[32][132]; } hf[2];
};

DINL void l0_prefetch(SL0::HF& f, const float* x, int n0, int tl){
  #pragma unroll
  for (int i = tl; i < 1024; i += 512){
    int row = i >> 5, q = i & 31;
    cpasync16(su32(&f.xb[row][q*4]), x + (size_t)(n0+row)*XDIM + q*4);
  }
}

__global__ __launch_bounds__(NTHR,1) void k_l0(const float* __restrict__ x,
                                               float* __restrict__ out,
                                               const float* __restrict__ w0,
                                               const float* __restrict__ b0){
  extern __shared__ __align__(16) char smem[];
  SL0& s = *reinterpret_cast<SL0*>(smem);
  const int tid = threadIdx.x, lane = tid & 31, warp = tid >> 5;
  const int h = warp >> 4, wl = warp & 15, tl = tid & 511;
  SL0::HF& f = s.hf[h];

  for (int i=tid;i<128*256;i+=NTHR) s.wp[i>>8][i&255] = WP0[i];
  for (int i=tid;i<256*128;i+=NTHR) s.wq[i>>7][i&127] = WQ0[i];
  if (tid < 128){ s.nw[tid] = w0[tid]; s.nb[tid] = b0[tid]; }

  const int vc = blockIdx.x*2 + h;
  l0_prefetch(f, x, vc*32, tl);
  cpcommit();
  __syncthreads();

  const unsigned aB = su32(&f.A[0][0]);
  const unsigned hB = su32(&f.H[0][0]);
  const unsigned pB = su32(&s.wp[0][0]);
  const unsigned qB = su32(&s.wq[0][0]);
  const int bid = h + 1;

  const int r0  = (wl >> 3) << 4;        // GEMM1: 16 warps, 16x32
  const int c0  = (wl & 7) << 5;
  const int r0b = (wl >> 2) << 4;        // GEMM2: 8 warps, 16x32
  const int c0b = (wl & 3) << 5;

  for (int tile = vc; tile < NT32; tile += VSTRIDE){
    const int n0 = tile * 32;
    cpwait0();
    barh(bid);
    { // ---- norm from xb ----
      const int row = tl >> 4, sub = tl & 15;
      float4 v0 = *reinterpret_cast<const float4*>(&f.xb[row][sub*8]);
      float4 v1 = *reinterpret_cast<const float4*>(&f.xb[row][sub*8+4]);
      float vv[8] = {v0.x,v0.y,v0.z,v0.w, v1.x,v1.y,v1.z,v1.w};
      float sm = 0.f, sq = 0.f;
      #pragma unroll
      for (int j=0;j<8;j++){ sm += vv[j]; sq += vv[j]*vv[j]; }
      #pragma unroll
      for (int o=1;o<16;o<<=1){ sm += __shfl_xor_sync(~0u, sm, o); sq += __shfl_xor_sync(~0u, sq, o); }
      float mu = sm * (1.f/128.f);
      float rinv = rsqrtf(sq*(1.f/128.f) - mu*mu + 1e-5f);
      const int cb = sub*8;
      __half2 hh[4];
      #pragma unroll
      for (int j=0;j<4;j++){
        float a0f = (vv[2*j]   - mu)*rinv*s.nw[cb+2*j]   + s.nb[cb+2*j];
        float a1f = (vv[2*j+1] - mu)*rinv*s.nw[cb+2*j+1] + s.nb[cb+2*j+1];
        hh[j] = __floats2half2_rn(a0f, a1f);
      }
      *reinterpret_cast<uint4*>(&f.A[row][cb]) = *reinterpret_cast<uint4*>(hh);
    }
    barh(bid);
    { // prefetch next tile for this half
      int nt = tile + VSTRIDE;
      if (nt < NT32) l0_prefetch(f, x, nt*32, tl);
      cpcommit();
    }
    { // ---- GEMM1 + sigmoid -> H (16 warps, 16x32) ----
      float acc[4][4];
      #pragma unroll
      for (int j=0;j<4;j++){ acc[j][0]=acc[j][1]=acc[j][2]=acc[j][3]=0.f; }
      #pragma unroll
      for (int k=0;k<8;k++){
        unsigned a0,a1,a2,a3;
        ldmx4(a0,a1,a2,a3, aaddr(aB,136,r0,k*16,lane));
        #pragma unroll
        for (int j=0;j<2;j++){
          unsigned b0,b1,b2,b3;
          ldmx4t(b0,b1,b2,b3, baddr(pB,264,k*16,c0+j*16,lane));
          mma16816(acc[2*j],   a0,a1,a2,a3, b0,b1);
          mma16816(acc[2*j+1], a0,a1,a2,a3, b2,b3);
        }
      }
      const int rr = r0 + (lane>>2), cc = c0 + ((lane&3)<<1);
      #pragma unroll
      for (int j=0;j<4;j++){
        *reinterpret_cast<__half2*>(&f.H[rr  ][cc+8*j]) = __floats2half2_rn(sigm(acc[j][0]), sigm(acc[j][1]));
        *reinterpret_cast<__half2*>(&f.H[rr+8][cc+8*j]) = __floats2half2_rn(sigm(acc[j][2]), sigm(acc[j][3]));
      }
    }
    barh(bid);
    if (wl < 8){ // ---- GEMM2 (8 warps, 16x32) + residual epilogue ----
      float acc2[4][4];
      #pragma unroll
      for (int j=0;j<4;j++){ acc2[j][0]=acc2[j][1]=acc2[j][2]=acc2[j][3]=0.f; }
      #pragma unroll
      for (int k=0;k<16;k++){
        unsigned a0,a1,a2,a3;
        ldmx4(a0,a1,a2,a3, aaddr(hB,264,r0b,k*16,lane));
        #pragma unroll
        for (int j=0;j<2;j++){
          unsigned b0,b1,b2,b3;
          ldmx4t(b0,b1,b2,b3, baddr(qB,136,k*16,c0b+j*16,lane));
          mma16816(acc2[2*j],   a0,a1,a2,a3, b0,b1);
          mma16816(acc2[2*j+1], a0,a1,a2,a3, b2,b3);
        }
      }
      const int rr = r0b + (lane>>2), ccl = (lane&3)<<1;
      #pragma unroll
      for (int t=0;t<4;t++){
        int c = c0b + 8*t + ccl;
        size_t i0 = (size_t)(n0+rr)*XDIM + c;
        size_t i1 = (size_t)(n0+rr+8)*XDIM + c;
        float2 xv0 = *reinterpret_cast<const float2*>(x + i0);
        float2 xv1 = *reinterpret_cast<const float2*>(x + i1);
        *reinterpret_cast<float2*>(out + i0) = make_float2(acc2[t][0]+xv0.x, acc2[t][1]+xv0.y);
        *reinterpret_cast<float2*>(out + i1) = make_float2(acc2[t][2]+xv1.x, acc2[t][3]+xv1.y);
      }
    }
  }
}

// ============================ l = 1 ============================
struct SL1 {
  float  nw[64];
  __half wp[64][136];
  __half wq[128][72];
  struct HF {
    float  xb[32][196];
    __half A[3][32][72];
    __half H[3][32][136];
  } hf[2];
};

DINL void l1_prefetch(SL1::HF& f, const float* x, int n0, int tl){
  #pragma unroll
  for (int i = tl; i < 1536; i += 512){
    int row = i/48, q = i - 48*row;
    cpasync16(su32(&f.xb[row][q*4]), x + (size_t)(n0+row)*XDIM + 128 + q*4);
  }
}

__global__ __launch_bounds__(NTHR,1) void k_l1(const float* __restrict__ x,
                                               float* __restrict__ out,
                                               const float* __restrict__ w1){
  extern __shared__ __align__(16) char smem[];
  SL1& s = *reinterpret_cast<SL1*>(smem);
  const int tid = threadIdx.x, lane = tid & 31, warp = tid >> 5;
  const int h = warp >> 4, wl = warp & 15, tl = tid & 511;
  SL1::HF& f = s.hf[h];

  for (int i=tid;i<64*128;i+=NTHR) s.wp[i>>7][i&127] = WP1[i];
  for (int i=tid;i<128*64;i+=NTHR) s.wq[i>>6][i&63]  = WQ1[i];
  if (tid < 64) s.nw[tid] = w1[tid];

  const int vc = blockIdx.x*2 + h;
  l1_prefetch(f, x, vc*32, tl);
  cpcommit();
  __syncthreads();

  const unsigned aB = su32(&f.A[0][0][0]);
  const unsigned hB = su32(&f.H[0][0][0]);
  const unsigned pB = su32(&s.wp[0][0]);
  const unsigned qB = su32(&s.wq[0][0]);
  const int bid = h + 1;

  const int g1r = (wl >> 3) << 4;    // GEMM1: 16 warps, 16x16, all m
  const int g1c = (wl & 7) << 4;
  const int g2r = (wl >> 2) << 4;    // GEMM2: 8 warps, 16x16, all m
  const int g2c = (wl & 3) << 4;

  for (int tile = vc; tile < NT32; tile += VSTRIDE){
    const int n0 = tile * 32;
    cpwait0();
    barh(bid);
    { // ---- RMS norm from xb -> A[m][n][c] ----
      const int row = tl >> 4, sub = tl & 15;
      const float4* xr = reinterpret_cast<const float4*>(&f.xb[row][sub*12]);
      float4 w[3];
      #pragma unroll
      for (int j=0;j<3;j++) w[j] = xr[j];
      float vv[12] = {w[0].x,w[0].y,w[0].z,w[0].w, w[1].x,w[1].y,w[1].z,w[1].w,
                      w[2].x,w[2].y,w[2].z,w[2].w};
      float sq = 0.f;
      #pragma unroll
      for (int j=0;j<12;j++) sq += vv[j]*vv[j];
      #pragma unroll
      for (int o=1;o<16;o<<=1) sq += __shfl_xor_sync(~0u, sq, o);
      float rinv = rsqrtf(sq*(1.f/64.f) + 1e-5f);
      const int c0 = sub*4;
      float nw0 = s.nw[c0], nw1 = s.nw[c0+1], nw2 = s.nw[c0+2], nw3 = s.nw[c0+3];
      #pragma unroll
      for (int m=0;m<3;m++){
        __half2 p0 = __floats2half2_rn(vv[m]*rinv*nw0,   vv[m+3]*rinv*nw1);
        __half2 p1 = __floats2half2_rn(vv[m+6]*rinv*nw2, vv[m+9]*rinv*nw3);
        *reinterpret_cast<__half2*>(&f.A[m][row][c0])   = p0;
        *reinterpret_cast<__half2*>(&f.A[m][row][c0+2]) = p1;
      }
    }
    barh(bid);
    { // prefetch next tile
      int nt = tile + VSTRIDE;
      if (nt < NT32) l1_prefetch(f, x, nt*32, tl);
      cpcommit();
    }
    { // ---- GEMM1 (m-batched) + in-register gate -> H[m][n][o] ----
      float acc[3][2][4];
      #pragma unroll
      for (int m=0;m<3;m++)
        #pragma unroll
        for (int j=0;j<2;j++){ acc[m][j][0]=acc[m][j][1]=acc[m][j][2]=acc[m][j][3]=0.f; }
      #pragma unroll
      for (int k=0;k<4;k++){
        unsigned b0,b1,b2,b3;
        ldmx4t(b0,b1,b2,b3, baddr(pB,136,k*16,g1c,lane));
        #pragma unroll
        for (int m=0;m<3;m++){
          unsigned a0,a1,a2,a3;
          ldmx4(a0,a1,a2,a3, aaddr(aB + m*4608u, 72, g1r, k*16, lane));
          mma16816(acc[m][0], a0,a1,a2,a3, b0,b1);
          mma16816(acc[m][1], a0,a1,a2,a3, b2,b3);
        }
      }
      const int rr = g1r + (lane>>2), ccl = (lane&3)<<1;
      #pragma unroll
      for (int j=0;j<2;j++){
        float g0 = sigm(sqrtf(acc[0][j][0]*acc[0][j][0] + acc[1][j][0]*acc[1][j][0] + acc[2][j][0]*acc[2][j][0] + 1e-12f));
        float g1 = sigm(sqrtf(acc[0][j][1]*acc[0][j][1] + acc[1][j][1]*acc[1][j][1] + acc[2][j][1]*acc[2][j][1] + 1e-12f));
        float g2 = sigm(sqrtf(acc[0][j][2]*acc[0][j][2] + acc[1][j][2]*acc[1][j][2] + acc[2][j][2]*acc[2][j][2] + 1e-12f));
        float g3 = sigm(sqrtf(acc[0][j][3]*acc[0][j][3] + acc[1][j][3]*acc[1][j][3] + acc[2][j][3]*acc[2][j][3] + 1e-12f));
        int c = g1c + 8*j + ccl;
        #pragma unroll
        for (int m=0;m<3;m++){
          *reinterpret_cast<__half2*>(&f.H[m][rr  ][c]) = __floats2half2_rn(acc[m][j][0]*g0, acc[m][j][1]*g1);
          *reinterpret_cast<__half2*>(&f.H[m][rr+8][c]) = __floats2half2_rn(acc[m][j][2]*g2, acc[m][j][3]*g3);
        }
      }
    }
    barh(bid);
    if (wl < 8){ // ---- GEMM2 (m-batched, 8 warps) + direct residual epilogue ----
      float acc2[3][2][4];
      #pragma unroll
      for (int m=0;m<3;m++)
        #pragma unroll
        for (int j=0;j<2;j++){ acc2[m][j][0]=acc2[m][j][1]=acc2[m][j][2]=acc2[m][j][3]=0.f; }
      #pragma unroll
      for (int k=0;k<8;k++){
        unsigned b0,b1,b2,b3;
        ldmx4t(b0,b1,b2,b3, baddr(qB,72,k*16,g2c,lane));
        #pragma unroll
        for (int m=0;m<3;m++){
          unsigned a0,a1,a2,a3;
          ldmx4(a0,a1,a2,a3, aaddr(hB + m*8704u, 136, g2r, k*16, lane));
          mma16816(acc2[m][0], a0,a1,a2,a3, b0,b1);
          mma16816(acc2[m][1], a0,a1,a2,a3, b2,b3);
        }
      }
      const int rr = g2r + (lane>>2), ccl = (lane&3)<<1;
      #pragma unroll
      for (int j=0;j<2;j++){
        int c = g2c + 8*j + ccl;          // even
        #pragma unroll
        for (int hh=0;hh<2;hh++){
          int n = rr + 8*hh;
          size_t off = (size_t)(n0+n)*XDIM + 128 + c*3;   // 6 consecutive floats
          float v[6] = { acc2[0][j][2*hh],   acc2[1][j][2*hh],   acc2[2][j][2*hh],
                         acc2[0][j][2*hh+1], acc2[1][j][2*hh+1], acc2[2][j][2*hh+1] };
          #pragma unroll
          for (int t=0;t<3;t++){
            float2 xv = *reinterpret_cast<const float2*>(x + off + 2*t);
            *reinterpret_cast<float2*>(out + off + 2*t) = make_float2(v[2*t]+xv.x, v[2*t+1]+xv.y);
          }
        }
      }
    }
  }
}

// ============================ l = 2 ============================
struct SL2 {
  float  nw[32];
  __half wp[32][72];
  __half wq[64][40];
  struct HF {
    float  xb[32][164];
    __half A[5][32][40];
    __half H[5][32][72];
  } hf[2];
};

DINL void l2_prefetch(SL2::HF& f, const float* x, int n0, int tl){
  #pragma unroll
  for (int i = tl; i < 1280; i += 512){
    int row = i/40, q = i - 40*row;
    cpasync16(su32(&f.xb[row][q*4]), x + (size_t)(n0+row)*XDIM + 320 + q*4);
  }
}

__global__ __launch_bounds__(NTHR,1) void k_l2(const float* __restrict__ x,
                                               float* __restrict__ out,
                                               const float* __restrict__ w2){
  extern __shared__ __align__(16) char smem[];
  SL2& s = *reinterpret_cast<SL2*>(smem);
  const int tid = threadIdx.x, lane = tid & 31, warp = tid >> 5;
  const int h = warp >> 4, wl = warp & 15, tl = tid & 511;
  SL2::HF& f = s.hf[h];

  for (int i=tid;i<32*64;i+=NTHR) s.wp[i>>6][i&63] = WP2[i];
  for (int i=tid;i<64*32;i+=NTHR) s.wq[i>>5][i&31] = WQ2[i];
  if (tid < 32) s.nw[tid] = w2[tid];

  const int vc = blockIdx.x*2 + h;
  l2_prefetch(f, x, vc*32, tl);
  cpcommit();
  __syncthreads();

  const unsigned aB = su32(&f.A[0][0][0]);
  const unsigned hB = su32(&f.H[0][0][0]);
  const unsigned pB = su32(&s.wp[0][0]);
  const unsigned qB = su32(&s.wq[0][0]);
  const int bid = h + 1;

  const int g1r = (wl >> 3) << 4;    // GEMM1: 16 warps, 16x8, all m
  const int g1c = (wl & 7) << 3;
  const int g2r = (wl >> 2) << 4;    // GEMM2: 8 warps, 16x8, all m
  const int g2c = (wl & 3) << 3;

  for (int tile = vc; tile < NT32; tile += VSTRIDE){
    const int n0 = tile * 32;
    cpwait0();
    barh(bid);
    { // ---- RMS norm from xb -> A[m][n][c] (half2 stores) ----
      const int row = tl >> 4, sub = tl & 15;
      const float2* xr = reinterpret_cast<const float2*>(&f.xb[row][sub*10]);
      float2 w[5];
      #pragma unroll
      for (int j=0;j<5;j++) w[j] = xr[j];
      float vv[10] = {w[0].x,w[0].y, w[1].x,w[1].y, w[2].x,w[2].y,
                      w[3].x,w[3].y, w[4].x,w[4].y};
      float sq = 0.f;
      #pragma unroll
      for (int j=0;j<10;j++) sq += vv[j]*vv[j];
      #pragma unroll
      for (int o=1;o<16;o<<=1) sq += __shfl_xor_sync(~0u, sq, o);
      float rinv = rsqrtf(sq*(1.f/32.f) + 1e-5f);
      const int c0 = sub*2;
      float nw0 = s.nw[c0], nw1 = s.nw[c0+1];
      #pragma unroll
      for (int m=0;m<5;m++){
        *reinterpret_cast<__half2*>(&f.A[m][row][c0]) =
          __floats2half2_rn(vv[m]*rinv*nw0, vv[m+5]*rinv*nw1);
      }
    }
    barh(bid);
    { // prefetch next tile
      int nt = tile + VSTRIDE;
      if (nt < NT32) l2_prefetch(f, x, nt*32, tl);
      cpcommit();
    }
    { // ---- GEMM1 (m-batched, 16x8) + in-register gate -> H[m][n][o] ----
      float acc[5][4];
      #pragma unroll
      for (int m=0;m<5;m++){ acc[m][0]=acc[m][1]=acc[m][2]=acc[m][3]=0.f; }
      #pragma unroll
      for (int k=0;k<2;k++){
        unsigned b0,b1;
        ldmx2t(b0,b1, b2addr(pB,72,k*16,g1c,lane));
        #pragma unroll
        for (int m=0;m<5;m++){
          unsigned a0,a1,a2,a3;
          ldmx4(a0,a1,a2,a3, aaddr(aB + m*2560u, 40, g1r, k*16, lane));
          mma16816(acc[m], a0,a1,a2,a3, b0,b1);
        }
      }
      const int rr = g1r + (lane>>2);
      const int c  = g1c + ((lane&3)<<1);
      float g0 = sigm(sqrtf(acc[0][0]*acc[0][0]+acc[1][0]*acc[1][0]+acc[2][0]*acc[2][0]+acc[3][0]*acc[3][0]+acc[4][0]*acc[4][0] + 1e-12f));
      float g1 = sigm(sqrtf(acc[0][1]*acc[0][1]+acc[1][1]*acc[1][1]+acc[2][1]*acc[2][1]+acc[3][1]*acc[3][1]+acc[4][1]*acc[4][1] + 1e-12f));
      float g2 = sigm(sqrtf(acc[0][2]*acc[0][2]+acc[1][2]*acc[1][2]+acc[2][2]*acc[2][2]+acc[3][2]*acc[3][2]+acc[4][2]*acc[4][2] + 1e-12f));
      float g3 = sigm(sqrtf(acc[0][3]*acc[0][3]+acc[1][3]*acc[1][3]+acc[2][3]*acc[2][3]+acc[3][3]*acc[3][3]+acc[4][3]*acc[4][3] + 1e-12f));
      #pragma unroll
      for (int m=0;m<5;m++){
        *reinterpret_cast<__half2*>(&f.H[m][rr  ][c]) = __floats2half2_rn(acc[m][0]*g0, acc[m][1]*g1);
        *reinterpret_cast<__half2*>(&f.H[m][rr+8][c]) = __floats2half2_rn(acc[m][2]*g2, acc[m][3]*g3);
      }
    }
    barh(bid);
    if (wl < 8){ // ---- GEMM2 (m-batched, 8 warps, 16x8) + direct residual epilogue ----
      float acc2[5][4];
      #pragma unroll
      for (int m=0;m<5;m++){ acc2[m][0]=acc2[m][1]=acc2[m][2]=acc2[m][3]=0.f; }
      #pragma unroll
      for (int k=0;k<4;k++){
        unsigned b0,b1;
        ldmx2t(b0,b1, b2addr(qB,40,k*16,g2c,lane));
        #pragma unroll
        for (int m=0;m<5;m++){
          unsigned a0,a1,a2,a3;
          ldmx4(a0,a1,a2,a3, aaddr(hB + m*4608u, 72, g2r, k*16, lane));
          mma16816(acc2[m], a0,a1,a2,a3, b0,b1);
        }
      }
      const int rr = g2r + (lane>>2);
      const int c  = g2c + ((lane&3)<<1);   // even
      #pragma unroll
      for (int hh=0;hh<2;hh++){
        int n = rr + 8*hh;
        size_t off = (size_t)(n0+n)*XDIM + 320 + c*5;   // 10 consecutive floats
        float v[10] = { acc2[0][2*hh],   acc2[1][2*hh],   acc2[2][2*hh],   acc2[3][2*hh],   acc2[4][2*hh],
                        acc2[0][2*hh+1], acc2[1][2*hh+1], acc2[2][2*hh+1], acc2[3][2*hh+1], acc2[4][2*hh+1] };
        #pragma unroll
        for (int t=0;t<5;t++){
          float2 xv = *reinterpret_cast<const float2*>(x + off + 2*t);
          *reinterpret_cast<float2*>(out + off + 2*t) = make_float2(v[2*t]+xv.x, v[2*t+1]+xv.y);
        }
      }
    }
  }
}

extern "C" void kernel_launch(void* const* d_in, const int* in_sizes, int n_in,
                              void* d_out, int out_size){
  const float* x   = (const float*)d_in[0];
  const float* nw0 = (const float*)d_in[1];
  const float* nb0 = (const float*)d_in[2];
  const float* nw1 = (const float*)d_in[3];
  const float* nw2 = (const float*)d_in[4];
  const float* p0  = (const float*)d_in[5];
  const float* p1  = (const float*)d_in[6];
  const float* p2  = (const float*)d_in[7];
  const float* q0  = (const float*)d_in[8];
  const float* q1  = (const float*)d_in[9];
  const float* q2  = (const float*)d_in[10];
  float* out = (float*)d_out;

  cudaFuncSetAttribute(k_l0, cudaFuncAttributeMaxDynamicSharedMemorySize, (int)sizeof(SL0));
  cudaFuncSetAttribute(k_l1, cudaFuncAttributeMaxDynamicSharedMemorySize, (int)sizeof(SL1));
  cudaFuncSetAttribute(k_l2, cudaFuncAttributeMaxDynamicSharedMemorySize, (int)sizeof(SL2));

  k_prep<<<96, 256>>>(p0, p1, p2, q0, q1, q2);
  k_l0<<<GRID, NTHR, sizeof(SL0)>>>(x, out, nw0, nb0);
  k_l1<<<GRID, NTHR, sizeof(SL1)>>>(x, out, nw1);
  k_l2<<<GRID, NTHR, sizeof(SL2)>>>(x, out, nw2);
}

// round 13
// speedup vs baseline: 1.1267x; 1.1267x over previous
#include <cuda_runtime.h>
#include <cuda_fp16.h>
#include <cstdint>

#define NROW 200000
#define XDIM 480
#define NT32 6250          // 200000/32
#define GRID 152
#define NTHR 1024
#define VSTRIDE 304        // 152 CTAs * 2 halves

#define DINL __device__ __forceinline__

DINL unsigned su32(const void* p){ return (unsigned)__cvta_generic_to_shared(p); }

DINL void cpasync16(unsigned dst, const void* src){
  asm volatile("cp.async.ca.shared.global [%0], [%1], 16;" :: "r"(dst), "l"(src));
}
DINL void cpcommit(){ asm volatile("cp.async.commit_group;" ::: "memory"); }
DINL void cpwait0(){ asm volatile("cp.async.wait_group 0;" ::: "memory"); }
DINL void barh(int id){ asm volatile("bar.sync %0, 512;" :: "r"(id) : "memory"); }

DINL void ldmx4(unsigned &r0,unsigned &r1,unsigned &r2,unsigned &r3, unsigned a){
  asm volatile("ldmatrix.sync.aligned.m8n8.x4.shared.b16 {%0,%1,%2,%3}, [%4];"
    : "=r"(r0),"=r"(r1),"=r"(r2),"=r"(r3) : "r"(a));
}
DINL void ldmx4t(unsigned &r0,unsigned &r1,unsigned &r2,unsigned &r3, unsigned a){
  asm volatile("ldmatrix.sync.aligned.m8n8.x4.trans.shared.b16 {%0,%1,%2,%3}, [%4];"
    : "=r"(r0),"=r"(r1),"=r"(r2),"=r"(r3) : "r"(a));
}
DINL void ldmx2t(unsigned &r0,unsigned &r1, unsigned a){
  asm volatile("ldmatrix.sync.aligned.m8n8.x2.trans.shared.b16 {%0,%1}, [%2];"
    : "=r"(r0),"=r"(r1) : "r"(a));
}
DINL void mma16816(float* c, unsigned a0,unsigned a1,unsigned a2,unsigned a3,
                   unsigned b0,unsigned b1){
  asm volatile("mma.sync.aligned.m16n8k16.row.col.f32.f16.f16.f32 "
    "{%0,%1,%2,%3}, {%4,%5,%6,%7}, {%8,%9}, {%0,%1,%2,%3};"
    : "+f"(c[0]),"+f"(c[1]),"+f"(c[2]),"+f"(c[3])
    : "r"(a0),"r"(a1),"r"(a2),"r"(a3),"r"(b0),"r"(b1));
}
DINL float sigm(float v){ return 1.f/(1.f+__expf(-v)); }

DINL unsigned aaddr(unsigned base, int stride, int r0, int k0, int lane){
  int r = r0 + (lane & 15);
  int c = k0 + ((lane >> 4) << 3);
  return base + (unsigned)((r * stride + c) << 1);
}
DINL unsigned baddr(unsigned base, int stride, int k0, int c0, int lane){
  int r = k0 + (lane & 7) + (((lane >> 3) & 1) << 3);
  int c = c0 + ((lane >> 4) << 3);
  return base + (unsigned)((r * stride + c) << 1);
}
DINL unsigned b2addr(unsigned base, int stride, int k0, int c0, int lane){
  int r = k0 + (lane & 15);
  return base + (unsigned)((r * stride + c0) << 1);
}

// fp16 weights with 1/sqrt(fan_in) folded
__device__ __half WP0[128*256];
__device__ __half WQ0[256*128];
__device__ __half WP1[64*128];
__device__ __half WQ1[128*64];
__device__ __half WP2[32*64];
__device__ __half WQ2[64*32];

__global__ void k_prep(const float* __restrict__ p0, const float* __restrict__ p1,
                       const float* __restrict__ p2, const float* __restrict__ q0,
                       const float* __restrict__ q1, const float* __restrict__ q2){
  int t = blockIdx.x*blockDim.x + threadIdx.x, st = gridDim.x*blockDim.x;
  for (int i=t;i<128*256;i+=st) WP0[i] = __float2half(p0[i]*0.08838834764831845f);
  for (int i=t;i<64*128;i+=st)  WP1[i] = __float2half(p1[i]*0.125f);
  for (int i=t;i<32*64;i+=st)   WP2[i] = __float2half(p2[i]*0.17677669529663687f);
  for (int i=t;i<256*128;i+=st) WQ0[i] = __float2half(q0[i]*0.0625f);
  for (int i=t;i<128*64;i+=st)  WQ1[i] = __float2half(q1[i]*0.08838834764831845f);
  for (int i=t;i<64*32;i+=st)   WQ2[i] = __float2half(q2[i]*0.125f);
}

// ============================ l = 0 ============================
struct SL0 {
  float  nw[128], nb[128];
  __half wp[128][264];
  __half wq[256][136];
  struct HF { __half A[32][136]; __half H[32][264]; float xb[32][132]; } hf[2];
};

DINL void l0_prefetch(SL0::HF& f, const float* x, int n0, int tl){
  #pragma unroll
  for (int i = tl; i < 1024; i += 512){
    int row = i >> 5, q = i & 31;
    cpasync16(su32(&f.xb[row][q*4]), x + (size_t)(n0+row)*XDIM + q*4);
  }
}

__global__ __launch_bounds__(NTHR,1) void k_l0(const float* __restrict__ x,
                                               float* __restrict__ out,
                                               const float* __restrict__ w0,
                                               const float* __restrict__ b0){
  extern __shared__ __align__(16) char smem[];
  SL0& s = *reinterpret_cast<SL0*>(smem);
  const int tid = threadIdx.x, lane = tid & 31, warp = tid >> 5;
  const int h = warp >> 4, wl = warp & 15, tl = tid & 511;
  SL0::HF& f = s.hf[h];

  for (int i=tid;i<128*256;i+=NTHR) s.wp[i>>8][i&255] = WP0[i];
  for (int i=tid;i<256*128;i+=NTHR) s.wq[i>>7][i&127] = WQ0[i];
  if (tid < 128){ s.nw[tid] = w0[tid]; s.nb[tid] = b0[tid]; }

  const int vc = blockIdx.x*2 + h;
  l0_prefetch(f, x, vc*32, tl);
  cpcommit();
  __syncthreads();

  const unsigned aB = su32(&f.A[0][0]);
  const unsigned hB = su32(&f.H[0][0]);
  const unsigned pB = su32(&s.wp[0][0]);
  const unsigned qB = su32(&s.wq[0][0]);
  const int bid = h + 1;

  const int r0  = (wl >> 3) << 4;        // GEMM1: 16 warps, 16x32
  const int c0  = (wl & 7) << 5;
  const int r0b = (wl >> 3) << 4;        // GEMM2: 16 warps, 16x16
  const int c0b = (wl & 7) << 4;

  for (int tile = vc; tile < NT32; tile += VSTRIDE){
    const int n0 = tile * 32;
    cpwait0();
    barh(bid);
    { // ---- norm from xb ----
      const int row = tl >> 4, sub = tl & 15;
      float4 v0 = *reinterpret_cast<const float4*>(&f.xb[row][sub*8]);
      float4 v1 = *reinterpret_cast<const float4*>(&f.xb[row][sub*8+4]);
      float vv[8] = {v0.x,v0.y,v0.z,v0.w, v1.x,v1.y,v1.z,v1.w};
      float sm = 0.f, sq = 0.f;
      #pragma unroll
      for (int j=0;j<8;j++){ sm += vv[j]; sq += vv[j]*vv[j]; }
      #pragma unroll
      for (int o=1;o<16;o<<=1){ sm += __shfl_xor_sync(~0u, sm, o); sq += __shfl_xor_sync(~0u, sq, o); }
      float mu = sm * (1.f/128.f);
      float rinv = rsqrtf(sq*(1.f/128.f) - mu*mu + 1e-5f);
      const int cb = sub*8;
      __half2 hh[4];
      #pragma unroll
      for (int j=0;j<4;j++){
        float a0f = (vv[2*j]   - mu)*rinv*s.nw[cb+2*j]   + s.nb[cb+2*j];
        float a1f = (vv[2*j+1] - mu)*rinv*s.nw[cb+2*j+1] + s.nb[cb+2*j+1];
        hh[j] = __floats2half2_rn(a0f, a1f);
      }
      *reinterpret_cast<uint4*>(&f.A[row][cb]) = *reinterpret_cast<uint4*>(hh);
    }
    barh(bid);
    { // prefetch next tile for this half
      int nt = tile + VSTRIDE;
      if (nt < NT32) l0_prefetch(f, x, nt*32, tl);
      cpcommit();
    }
    { // ---- GEMM1 + sigmoid -> H (16 warps, 16x32) ----
      float acc[4][4];
      #pragma unroll
      for (int j=0;j<4;j++){ acc[j][0]=acc[j][1]=acc[j][2]=acc[j][3]=0.f; }
      #pragma unroll
      for (int k=0;k<8;k++){
        unsigned a0,a1,a2,a3;
        ldmx4(a0,a1,a2,a3, aaddr(aB,136,r0,k*16,lane));
        #pragma unroll
        for (int j=0;j<2;j++){
          unsigned b0,b1,b2,b3;
          ldmx4t(b0,b1,b2,b3, baddr(pB,264,k*16,c0+j*16,lane));
          mma16816(acc[2*j],   a0,a1,a2,a3, b0,b1);
          mma16816(acc[2*j+1], a0,a1,a2,a3, b2,b3);
        }
      }
      const int rr = r0 + (lane>>2), cc = c0 + ((lane&3)<<1);
      #pragma unroll
      for (int j=0;j<4;j++){
        *reinterpret_cast<__half2*>(&f.H[rr  ][cc+8*j]) = __floats2half2_rn(sigm(acc[j][0]), sigm(acc[j][1]));
        *reinterpret_cast<__half2*>(&f.H[rr+8][cc+8*j]) = __floats2half2_rn(sigm(acc[j][2]), sigm(acc[j][3]));
      }
    }
    barh(bid);
    { // ---- GEMM2 (16 warps, 16x16) + residual epilogue ----
      float acc2[2][4];
      #pragma unroll
      for (int j=0;j<2;j++){ acc2[j][0]=acc2[j][1]=acc2[j][2]=acc2[j][3]=0.f; }
      #pragma unroll
      for (int k=0;k<16;k++){
        unsigned a0,a1,a2,a3;
        ldmx4(a0,a1,a2,a3, aaddr(hB,264,r0b,k*16,lane));
        unsigned b0,b1,b2,b3;
        ldmx4t(b0,b1,b2,b3, baddr(qB,136,k*16,c0b,lane));
        mma16816(acc2[0], a0,a1,a2,a3, b0,b1);
        mma16816(acc2[1], a0,a1,a2,a3, b2,b3);
      }
      const int rr = r0b + (lane>>2), ccl = (lane&3)<<1;
      #pragma unroll
      for (int t=0;t<2;t++){
        int c = c0b + 8*t + ccl;
        size_t i0 = (size_t)(n0+rr)*XDIM + c;
        size_t i1 = (size_t)(n0+rr+8)*XDIM + c;
        float2 xv0 = *reinterpret_cast<const float2*>(x + i0);
        float2 xv1 = *reinterpret_cast<const float2*>(x + i1);
        *reinterpret_cast<float2*>(out + i0) = make_float2(acc2[t][0]+xv0.x, acc2[t][1]+xv0.y);
        *reinterpret_cast<float2*>(out + i1) = make_float2(acc2[t][2]+xv1.x, acc2[t][3]+xv1.y);
      }
    }
  }
}

// ============================ l = 1 ============================
struct SL1 {
  float  nw[64];
  __half wp[64][136];
  __half wq[128][72];
  struct HF {
    float  xb[32][196];
    __half A[3][32][72];
    __half H[3][32][136];
    float  ob[32][196];
  } hf[2];
};

DINL void l1_prefetch(SL1::HF& f, const float* x, int n0, int tl){
  #pragma unroll
  for (int i = tl; i < 1536; i += 512){
    int row = i/48, q = i - 48*row;
    cpasync16(su32(&f.xb[row][q*4]), x + (size_t)(n0+row)*XDIM + 128 + q*4);
  }
}

__global__ __launch_bounds__(NTHR,1) void k_l1(const float* __restrict__ x,
                                               float* __restrict__ out,
                                               const float* __restrict__ w1){
  extern __shared__ __align__(16) char smem[];
  SL1& s = *reinterpret_cast<SL1*>(smem);
  const int tid = threadIdx.x, lane = tid & 31, warp = tid >> 5;
  const int h = warp >> 4, wl = warp & 15, tl = tid & 511;
  SL1::HF& f = s.hf[h];

  for (int i=tid;i<64*128;i+=NTHR) s.wp[i>>7][i&127] = WP1[i];
  for (int i=tid;i<128*64;i+=NTHR) s.wq[i>>6][i&63]  = WQ1[i];
  if (tid < 64) s.nw[tid] = w1[tid];

  const int vc = blockIdx.x*2 + h;
  l1_prefetch(f, x, vc*32, tl);
  cpcommit();
  __syncthreads();

  const unsigned aB = su32(&f.A[0][0][0]);
  const unsigned hB = su32(&f.H[0][0][0]);
  const unsigned pB = su32(&s.wp[0][0]);
  const unsigned qB = su32(&s.wq[0][0]);
  const int bid = h + 1;

  const int g1r = (wl >> 3) << 4;    // GEMM1: 16 warps, 16x16, all m
  const int g1c = (wl & 7) << 4;
  const int g2r = (wl >> 3) << 4;    // GEMM2: 16 warps, 16x8, all m
  const int g2c = (wl & 7) << 3;

  for (int tile = vc; tile < NT32; tile += VSTRIDE){
    const int n0 = tile * 32;
    cpwait0();
    barh(bid);
    { // ---- RMS norm from xb -> A[m][n][c] ----
      const int row = tl >> 4, sub = tl & 15;
      const float4* xr = reinterpret_cast<const float4*>(&f.xb[row][sub*12]);
      float4 w[3];
      #pragma unroll
      for (int j=0;j<3;j++) w[j] = xr[j];
      float vv[12] = {w[0].x,w[0].y,w[0].z,w[0].w, w[1].x,w[1].y,w[1].z,w[1].w,
                      w[2].x,w[2].y,w[2].z,w[2].w};
      float sq = 0.f;
      #pragma unroll
      for (int j=0;j<12;j++) sq += vv[j]*vv[j];
      #pragma unroll
      for (int o=1;o<16;o<<=1) sq += __shfl_xor_sync(~0u, sq, o);
      float rinv = rsqrtf(sq*(1.f/64.f) + 1e-5f);
      const int c0 = sub*4;
      float nw0 = s.nw[c0], nw1 = s.nw[c0+1], nw2 = s.nw[c0+2], nw3 = s.nw[c0+3];
      #pragma unroll
      for (int m=0;m<3;m++){
        __half2 p0 = __floats2half2_rn(vv[m]*rinv*nw0,   vv[m+3]*rinv*nw1);
        __half2 p1 = __floats2half2_rn(vv[m+6]*rinv*nw2, vv[m+9]*rinv*nw3);
        *reinterpret_cast<__half2*>(&f.A[m][row][c0])   = p0;
        *reinterpret_cast<__half2*>(&f.A[m][row][c0+2]) = p1;
      }
    }
    barh(bid);
    { // prefetch next tile
      int nt = tile + VSTRIDE;
      if (nt < NT32) l1_prefetch(f, x, nt*32, tl);
      cpcommit();
    }
    { // ---- GEMM1 (m-batched) + in-register gate -> H[m][n][o] ----
      float acc[3][2][4];
      #pragma unroll
      for (int m=0;m<3;m++)
        #pragma unroll
        for (int j=0;j<2;j++){ acc[m][j][0]=acc[m][j][1]=acc[m][j][2]=acc[m][j][3]=0.f; }
      #pragma unroll
      for (int k=0;k<4;k++){
        unsigned b0,b1,b2,b3;
        ldmx4t(b0,b1,b2,b3, baddr(pB,136,k*16,g1c,lane));
        #pragma unroll
        for (int m=0;m<3;m++){
          unsigned a0,a1,a2,a3;
          ldmx4(a0,a1,a2,a3, aaddr(aB + m*4608u, 72, g1r, k*16, lane));
          mma16816(acc[m][0], a0,a1,a2,a3, b0,b1);
          mma16816(acc[m][1], a0,a1,a2,a3, b2,b3);
        }
      }
      const int rr = g1r + (lane>>2), ccl = (lane&3)<<1;
      #pragma unroll
      for (int j=0;j<2;j++){
        float g0 = sigm(sqrtf(acc[0][j][0]*acc[0][j][0] + acc[1][j][0]*acc[1][j][0] + acc[2][j][0]*acc[2][j][0] + 1e-12f));
        float g1 = sigm(sqrtf(acc[0][j][1]*acc[0][j][1] + acc[1][j][1]*acc[1][j][1] + acc[2][j][1]*acc[2][j][1] + 1e-12f));
        float g2 = sigm(sqrtf(acc[0][j][2]*acc[0][j][2] + acc[1][j][2]*acc[1][j][2] + acc[2][j][2]*acc[2][j][2] + 1e-12f));
        float g3 = sigm(sqrtf(acc[0][j][3]*acc[0][j][3] + acc[1][j][3]*acc[1][j][3] + acc[2][j][3]*acc[2][j][3] + 1e-12f));
        int c = g1c + 8*j + ccl;
        #pragma unroll
        for (int m=0;m<3;m++){
          *reinterpret_cast<__half2*>(&f.H[m][rr  ][c]) = __floats2half2_rn(acc[m][j][0]*g0, acc[m][j][1]*g1);
          *reinterpret_cast<__half2*>(&f.H[m][rr+8][c]) = __floats2half2_rn(acc[m][j][2]*g2, acc[m][j][3]*g3);
        }
      }
    }
    barh(bid);
    { // ---- GEMM2 (m-batched, 16 warps, 16x8) -> ob ----
      float acc2[3][4];
      #pragma unroll
      for (int m=0;m<3;m++){ acc2[m][0]=acc2[m][1]=acc2[m][2]=acc2[m][3]=0.f; }
      #pragma unroll
      for (int k=0;k<8;k++){
        unsigned b0,b1;
        ldmx2t(b0,b1, b2addr(qB,72,k*16,g2c,lane));
        #pragma unroll
        for (int m=0;m<3;m++){
          unsigned a0,a1,a2,a3;
          ldmx4(a0,a1,a2,a3, aaddr(hB + m*8704u, 136, g2r, k*16, lane));
          mma16816(acc2[m], a0,a1,a2,a3, b0,b1);
        }
      }
      const int rr = g2r + (lane>>2);
      const int c  = g2c + ((lane&3)<<1);
      #pragma unroll
      for (int hh=0;hh<2;hh++){
        int n = rr + 8*hh;
        #pragma unroll
        for (int m=0;m<3;m++){
          f.ob[n][c*3 + m]     = acc2[m][2*hh];
          f.ob[n][(c+1)*3 + m] = acc2[m][2*hh+1];
        }
      }
    }
    barh(bid);
    { // ---- coalesced store + residual ----
      #pragma unroll
      for (int i=0;i<3;i++){
        int idx = tl + i*512;          // 32 rows * 48 float4 = 1536
        int row = idx/48, q = idx - 48*row;
        float4 v = *reinterpret_cast<const float4*>(&f.ob[row][q*4]);
        const float4 xv = *reinterpret_cast<const float4*>(x + (size_t)(n0+row)*XDIM + 128 + q*4);
        *reinterpret_cast<float4*>(out + (size_t)(n0+row)*XDIM + 128 + q*4) =
          make_float4(v.x+xv.x, v.y+xv.y, v.z+xv.z, v.w+xv.w);
      }
    }
  }
}

// ============================ l = 2 (round-10, unchanged) ============================
struct SL2 {
  float  nw[32];
  __half wp[32][72];
  __half wq[64][40];
  struct HF {
    float  xb[32][164];
    __half A[5][32][40];
    __half H[5][32][72];
    float  ob[32][164];
  } hf[2];
};

DINL void l2_prefetch(SL2::HF& f, const float* x, int n0, int tl){
  #pragma unroll
  for (int i = tl; i < 1280; i += 512){
    int row = i/40, q = i - 40*row;
    cpasync16(su32(&f.xb[row][q*4]), x + (size_t)(n0+row)*XDIM + 320 + q*4);
  }
}

__global__ __launch_bounds__(NTHR,1) void k_l2(const float* __restrict__ x,
                                               float* __restrict__ out,
                                               const float* __restrict__ w2){
  extern __shared__ __align__(16) char smem[];
  SL2& s = *reinterpret_cast<SL2*>(smem);
  const int tid = threadIdx.x, lane = tid & 31, warp = tid >> 5;
  const int h = warp >> 4, wl = warp & 15, tl = tid & 511;
  SL2::HF& f = s.hf[h];

  for (int i=tid;i<32*64;i+=NTHR) s.wp[i>>6][i&63] = WP2[i];
  for (int i=tid;i<64*32;i+=NTHR) s.wq[i>>5][i&31] = WQ2[i];
  if (tid < 32) s.nw[tid] = w2[tid];

  const int vc = blockIdx.x*2 + h;
  l2_prefetch(f, x, vc*32, tl);
  cpcommit();
  __syncthreads();

  const unsigned aB = su32(&f.A[0][0][0]);
  const unsigned hB = su32(&f.H[0][0][0]);
  const unsigned pB = su32(&s.wp[0][0]);
  const unsigned qB = su32(&s.wq[0][0]);
  const int bid = h + 1;

  const int g1r = (wl >> 3) << 4;    // GEMM1: 16 warps, 16x8, all m
  const int g1c = (wl & 7) << 3;
  const int g2r = (wl >> 2) << 4;    // GEMM2: 8 warps, 16x8, all m
  const int g2c = (wl & 3) << 3;

  for (int tile = vc; tile < NT32; tile += VSTRIDE){
    const int n0 = tile * 32;
    cpwait0();
    barh(bid);
    { // ---- RMS norm from xb -> A[m][n][c] (half2 stores) ----
      const int row = tl >> 4, sub = tl & 15;
      const float2* xr = reinterpret_cast<const float2*>(&f.xb[row][sub*10]);
      float2 w[5];
      #pragma unroll
      for (int j=0;j<5;j++) w[j] = xr[j];
      float vv[10] = {w[0].x,w[0].y, w[1].x,w[1].y, w[2].x,w[2].y,
                      w[3].x,w[3].y, w[4].x,w[4].y};
      float sq = 0.f;
      #pragma unroll
      for (int j=0;j<10;j++) sq += vv[j]*vv[j];
      #pragma unroll
      for (int o=1;o<16;o<<=1) sq += __shfl_xor_sync(~0u, sq, o);
      float rinv = rsqrtf(sq*(1.f/32.f) + 1e-5f);
      const int c0 = sub*2;
      float nw0 = s.nw[c0], nw1 = s.nw[c0+1];
      #pragma unroll
      for (int m=0;m<5;m++){
        *reinterpret_cast<__half2*>(&f.A[m][row][c0]) =
          __floats2half2_rn(vv[m]*rinv*nw0, vv[m+5]*rinv*nw1);
      }
    }
    barh(bid);
    { // prefetch next tile
      int nt = tile + VSTRIDE;
      if (nt < NT32) l2_prefetch(f, x, nt*32, tl);
      cpcommit();
    }
    { // ---- GEMM1 (m-batched, 16x8) + in-register gate -> H[m][n][o] ----
      float acc[5][4];
      #pragma unroll
      for (int m=0;m<5;m++){ acc[m][0]=acc[m][1]=acc[m][2]=acc[m][3]=0.f; }
      #pragma unroll
      for (int k=0;k<2;k++){
        unsigned b0,b1;
        ldmx2t(b0,b1, b2addr(pB,72,k*16,g1c,lane));
        #pragma unroll
        for (int m=0;m<5;m++){
          unsigned a0,a1,a2,a3;
          ldmx4(a0,a1,a2,a3, aaddr(aB + m*2560u, 40, g1r, k*16, lane));
          mma16816(acc[m], a0,a1,a2,a3, b0,b1);
        }
      }
      const int rr = g1r + (lane>>2);
      const int c  = g1c + ((lane&3)<<1);
      float g0 = sigm(sqrtf(acc[0][0]*acc[0][0]+acc[1][0]*acc[1][0]+acc[2][0]*acc[2][0]+acc[3][0]*acc[3][0]+acc[4][0]*acc[4][0] + 1e-12f));
      float g1 = sigm(sqrtf(acc[0][1]*acc[0][1]+acc[1][1]*acc[1][1]+acc[2][1]*acc[2][1]+acc[3][1]*acc[3][1]+acc[4][1]*acc[4][1] + 1e-12f));
      float g2 = sigm(sqrtf(acc[0][2]*acc[0][2]+acc[1][2]*acc[1][2]+acc[2][2]*acc[2][2]+acc[3][2]*acc[3][2]+acc[4][2]*acc[4][2] + 1e-12f));
      float g3 = sigm(sqrtf(acc[0][3]*acc[0][3]+acc[1][3]*acc[1][3]+acc[2][3]*acc[2][3]+acc[3][3]*acc[3][3]+acc[4][3]*acc[4][3] + 1e-12f));
      #pragma unroll
      for (int m=0;m<5;m++){
        *reinterpret_cast<__half2*>(&f.H[m][rr  ][c]) = __floats2half2_rn(acc[m][0]*g0, acc[m][1]*g1);
        *reinterpret_cast<__half2*>(&f.H[m][rr+8][c]) = __floats2half2_rn(acc[m][2]*g2, acc[m][3]*g3);
      }
    }
    barh(bid);
    if (wl < 8){ // ---- GEMM2 (m-batched, 8 warps, 16x8) -> ob ----
      float acc2[5][4];
      #pragma unroll
      for (int m=0;m<5;m++){ acc2[m][0]=acc2[m][1]=acc2[m][2]=acc2[m][3]=0.f; }
      #pragma unroll
      for (int k=0;k<4;k++){
        unsigned b0,b1;
        ldmx2t(b0,b1, b2addr(qB,40,k*16,g2c,lane));
        #pragma unroll
        for (int m=0;m<5;m++){
          unsigned a0,a1,a2,a3;
          ldmx4(a0,a1,a2,a3, aaddr(hB + m*4608u, 72, g2r, k*16, lane));
          mma16816(acc2[m], a0,a1,a2,a3, b0,b1);
        }
      }
      const int rr = g2r + (lane>>2);
      const int c  = g2c + ((lane&3)<<1);
      #pragma unroll
      for (int hh=0;hh<2;hh++){
        int n = rr + 8*hh;
        #pragma unroll
        for (int m=0;m<5;m++){
          f.ob[n][c*5 + m]     = acc2[m][2*hh];
          f.ob[n][(c+1)*5 + m] = acc2[m][2*hh+1];
        }
      }
    }
    barh(bid);
    { // ---- coalesced store + residual ----
      #pragma unroll
      for (int i=0;i<3;i++){
        int idx = tl + i*512;          // 32 rows * 40 float4 = 1280
        if (idx < 1280){
          int row = idx/40, q = idx - 40*row;
          float4 v = *reinterpret_cast<const float4*>(&f.ob[row][q*4]);
          const float4 xv = *reinterpret_cast<const float4*>(x + (size_t)(n0+row)*XDIM + 320 + q*4);
          *reinterpret_cast<float4*>(out + (size_t)(n0+row)*XDIM + 320 + q*4) =
            make_float4(v.x+xv.x, v.y+xv.y, v.z+xv.z, v.w+xv.w);
        }
      }
    }
  }
}

extern "C" void kernel_launch(void* const* d_in, const int* in_sizes, int n_in,
                              void* d_out, int out_size){
  const float* x   = (const float*)d_in[0];
  const float* nw0 = (const float*)d_in[1];
  const float* nb0 = (const float*)d_in[2];
  const float* nw1 = (const float*)d_in[3];
  const float* nw2 = (const float*)d_in[4];
  const float* p0  = (const float*)d_in[5];
  const float* p1  = (const float*)d_in[6];
  const float* p2  = (const float*)d_in[7];
  const float* q0  = (const float*)d_in[8];
  const float* q1  = (const float*)d_in[9];
  const float* q2  = (const float*)d_in[10];
  float* out = (float*)d_out;

  cudaFuncSetAttribute(k_l0, cudaFuncAttributeMaxDynamicSharedMemorySize, (int)sizeof(SL0));
  cudaFuncSetAttribute(k_l1, cudaFuncAttributeMaxDynamicSharedMemorySize, (int)sizeof(SL1));
  cudaFuncSetAttribute(k_l2, cudaFuncAttributeMaxDynamicSharedMemorySize, (int)sizeof(SL2));

  k_prep<<<96, 256>>>(p0, p1, p2, q0, q1, q2);
  k_l0<<<GRID, NTHR, sizeof(SL0)>>>(x, out, nw0, nb0);
  k_l1<<<GRID, NTHR, sizeof(SL1)>>>(x, out, nw1);
  k_l2<<<GRID, NTHR, sizeof(SL2)>>>(x, out, nw2);
}

// round 14
// speedup vs baseline: 1.2659x; 1.1235x over previous
#include <cuda_runtime.h>
#include <cuda_fp16.h>
#include <cstdint>

#define NROW 200000
#define XDIM 480
#define NT16 12500         // 200000/16
#define GRID 152
#define NTHR 1024
#define VSTRIDE 608        // 152 CTAs * 4 quarters

#define DINL __device__ __forceinline__

DINL unsigned su32(const void* p){ return (unsigned)__cvta_generic_to_shared(p); }

DINL void cpasync16(unsigned dst, const void* src){
  asm volatile("cp.async.ca.shared.global [%0], [%1], 16;" :: "r"(dst), "l"(src));
}
DINL void cpcommit(){ asm volatile("cp.async.commit_group;" ::: "memory"); }
DINL void cpwait0(){ asm volatile("cp.async.wait_group 0;" ::: "memory"); }
DINL void barq(int id){ asm volatile("bar.sync %0, 256;" :: "r"(id) : "memory"); }

DINL void ldmx4(unsigned &r0,unsigned &r1,unsigned &r2,unsigned &r3, unsigned a){
  asm volatile("ldmatrix.sync.aligned.m8n8.x4.shared.b16 {%0,%1,%2,%3}, [%4];"
    : "=r"(r0),"=r"(r1),"=r"(r2),"=r"(r3) : "r"(a));
}
DINL void ldmx4t(unsigned &r0,unsigned &r1,unsigned &r2,unsigned &r3, unsigned a){
  asm volatile("ldmatrix.sync.aligned.m8n8.x4.trans.shared.b16 {%0,%1,%2,%3}, [%4];"
    : "=r"(r0),"=r"(r1),"=r"(r2),"=r"(r3) : "r"(a));
}
DINL void ldmx2t(unsigned &r0,unsigned &r1, unsigned a){
  asm volatile("ldmatrix.sync.aligned.m8n8.x2.trans.shared.b16 {%0,%1}, [%2];"
    : "=r"(r0),"=r"(r1) : "r"(a));
}
DINL void mma16816(float* c, unsigned a0,unsigned a1,unsigned a2,unsigned a3,
                   unsigned b0,unsigned b1){
  asm volatile("mma.sync.aligned.m16n8k16.row.col.f32.f16.f16.f32 "
    "{%0,%1,%2,%3}, {%4,%5,%6,%7}, {%8,%9}, {%0,%1,%2,%3};"
    : "+f"(c[0]),"+f"(c[1]),"+f"(c[2]),"+f"(c[3])
    : "r"(a0),"r"(a1),"r"(a2),"r"(a3),"r"(b0),"r"(b1));
}
DINL float sigm(float v){ return 1.f/(1.f+__expf(-v)); }

DINL unsigned aaddr(unsigned base, int stride, int r0, int k0, int lane){
  int r = r0 + (lane & 15);
  int c = k0 + ((lane >> 4) << 3);
  return base + (unsigned)((r * stride + c) << 1);
}
DINL unsigned baddr(unsigned base, int stride, int k0, int c0, int lane){
  int r = k0 + (lane & 7) + (((lane >> 3) & 1) << 3);
  int c = c0 + ((lane >> 4) << 3);
  return base + (unsigned)((r * stride + c) << 1);
}
DINL unsigned b2addr(unsigned base, int stride, int k0, int c0, int lane){
  int r = k0 + (lane & 15);
  return base + (unsigned)((r * stride + c0) << 1);
}

// fp16 weights with 1/sqrt(fan_in) folded
__device__ __half WP0[128*256];
__device__ __half WQ0[256*128];
__device__ __half WP1[64*128];
__device__ __half WQ1[128*64];
__device__ __half WP2[32*64];
__device__ __half WQ2[64*32];

__global__ void k_prep(const float* __restrict__ p0, const float* __restrict__ p1,
                       const float* __restrict__ p2, const float* __restrict__ q0,
                       const float* __restrict__ q1, const float* __restrict__ q2){
  int t = blockIdx.x*blockDim.x + threadIdx.x, st = gridDim.x*blockDim.x;
  for (int i=t;i<128*256;i+=st) WP0[i] = __float2half(p0[i]*0.08838834764831845f);
  for (int i=t;i<64*128;i+=st)  WP1[i] = __float2half(p1[i]*0.125f);
  for (int i=t;i<32*64;i+=st)   WP2[i] = __float2half(p2[i]*0.17677669529663687f);
  for (int i=t;i<256*128;i+=st) WQ0[i] = __float2half(q0[i]*0.0625f);
  for (int i=t;i<128*64;i+=st)  WQ1[i] = __float2half(q1[i]*0.08838834764831845f);
  for (int i=t;i<64*32;i+=st)   WQ2[i] = __float2half(q2[i]*0.125f);
}

// ============================ l = 0 ============================
struct SL0 {
  float  nw[128], nb[128];
  __half wp[128][264];
  __half wq[256][136];
  struct HF { __half A[16][136]; __half H[16][264]; float xb[16][132]; } hf[4];
};

DINL void l0_prefetch(SL0::HF& f, const float* x, int n0, int tl){
  #pragma unroll
  for (int i = tl; i < 512; i += 256){
    int row = i >> 5, q = i & 31;
    cpasync16(su32(&f.xb[row][q*4]), x + (size_t)(n0+row)*XDIM + q*4);
  }
}

__global__ __launch_bounds__(NTHR,1) void k_l0(const float* __restrict__ x,
                                               float* __restrict__ out,
                                               const float* __restrict__ w0,
                                               const float* __restrict__ b0){
  extern __shared__ __align__(16) char smem[];
  SL0& s = *reinterpret_cast<SL0*>(smem);
  const int tid = threadIdx.x, lane = tid & 31, warp = tid >> 5;
  const int qg = warp >> 3, wl = warp & 7, tl = tid & 255;
  SL0::HF& f = s.hf[qg];

  for (int i=tid;i<128*256;i+=NTHR) s.wp[i>>8][i&255] = WP0[i];
  for (int i=tid;i<256*128;i+=NTHR) s.wq[i>>7][i&127] = WQ0[i];
  if (tid < 128){ s.nw[tid] = w0[tid]; s.nb[tid] = b0[tid]; }

  const int vc = blockIdx.x*4 + qg;
  l0_prefetch(f, x, vc*16, tl);
  cpcommit();
  __syncthreads();

  const unsigned aB = su32(&f.A[0][0]);
  const unsigned hB = su32(&f.H[0][0]);
  const unsigned pB = su32(&s.wp[0][0]);
  const unsigned qB = su32(&s.wq[0][0]);
  const int bid = qg + 1;

  const int c0  = wl << 5;           // GEMM1: 8 warps, 16x32
  const int c0b = wl << 5;           // GEMM2: 4 warps (wl<4), 16x32

  for (int tile = vc; tile < NT16; tile += VSTRIDE){
    const int n0 = tile * 16;
    cpwait0();
    barq(bid);
    { // ---- norm from xb ----
      const int row = tl >> 4, sub = tl & 15;
      float4 v0 = *reinterpret_cast<const float4*>(&f.xb[row][sub*8]);
      float4 v1 = *reinterpret_cast<const float4*>(&f.xb[row][sub*8+4]);
      float vv[8] = {v0.x,v0.y,v0.z,v0.w, v1.x,v1.y,v1.z,v1.w};
      float sm = 0.f, sq = 0.f;
      #pragma unroll
      for (int j=0;j<8;j++){ sm += vv[j]; sq += vv[j]*vv[j]; }
      #pragma unroll
      for (int o=1;o<16;o<<=1){ sm += __shfl_xor_sync(~0u, sm, o); sq += __shfl_xor_sync(~0u, sq, o); }
      float mu = sm * (1.f/128.f);
      float rinv = rsqrtf(sq*(1.f/128.f) - mu*mu + 1e-5f);
      const int cb = sub*8;
      __half2 hh[4];
      #pragma unroll
      for (int j=0;j<4;j++){
        float a0f = (vv[2*j]   - mu)*rinv*s.nw[cb+2*j]   + s.nb[cb+2*j];
        float a1f = (vv[2*j+1] - mu)*rinv*s.nw[cb+2*j+1] + s.nb[cb+2*j+1];
        hh[j] = __floats2half2_rn(a0f, a1f);
      }
      *reinterpret_cast<uint4*>(&f.A[row][cb]) = *reinterpret_cast<uint4*>(hh);
    }
    barq(bid);
    { // prefetch next tile for this quarter
      int nt = tile + VSTRIDE;
      if (nt < NT16) l0_prefetch(f, x, nt*16, tl);
      cpcommit();
    }
    { // ---- GEMM1 + sigmoid -> H (8 warps, 16x32) ----
      float acc[4][4];
      #pragma unroll
      for (int j=0;j<4;j++){ acc[j][0]=acc[j][1]=acc[j][2]=acc[j][3]=0.f; }
      #pragma unroll
      for (int k=0;k<8;k++){
        unsigned a0,a1,a2,a3;
        ldmx4(a0,a1,a2,a3, aaddr(aB,136,0,k*16,lane));
        #pragma unroll
        for (int j=0;j<2;j++){
          unsigned b0,b1,b2,b3;
          ldmx4t(b0,b1,b2,b3, baddr(pB,264,k*16,c0+j*16,lane));
          mma16816(acc[2*j],   a0,a1,a2,a3, b0,b1);
          mma16816(acc[2*j+1], a0,a1,a2,a3, b2,b3);
        }
      }
      const int rr = lane>>2, cc = c0 + ((lane&3)<<1);
      #pragma unroll
      for (int j=0;j<4;j++){
        *reinterpret_cast<__half2*>(&f.H[rr  ][cc+8*j]) = __floats2half2_rn(sigm(acc[j][0]), sigm(acc[j][1]));
        *reinterpret_cast<__half2*>(&f.H[rr+8][cc+8*j]) = __floats2half2_rn(sigm(acc[j][2]), sigm(acc[j][3]));
      }
    }
    barq(bid);
    if (wl < 4){ // ---- GEMM2 (4 warps, 16x32) + residual epilogue ----
      float acc2[4][4];
      #pragma unroll
      for (int j=0;j<4;j++){ acc2[j][0]=acc2[j][1]=acc2[j][2]=acc2[j][3]=0.f; }
      #pragma unroll
      for (int k=0;k<16;k++){
        unsigned a0,a1,a2,a3;
        ldmx4(a0,a1,a2,a3, aaddr(hB,264,0,k*16,lane));
        #pragma unroll
        for (int j=0;j<2;j++){
          unsigned b0,b1,b2,b3;
          ldmx4t(b0,b1,b2,b3, baddr(qB,136,k*16,c0b+j*16,lane));
          mma16816(acc2[2*j],   a0,a1,a2,a3, b0,b1);
          mma16816(acc2[2*j+1], a0,a1,a2,a3, b2,b3);
        }
      }
      const int rr = lane>>2, ccl = (lane&3)<<1;
      #pragma unroll
      for (int t=0;t<4;t++){
        int c = c0b + 8*t + ccl;
        size_t i0 = (size_t)(n0+rr)*XDIM + c;
        size_t i1 = (size_t)(n0+rr+8)*XDIM + c;
        float2 xv0 = *reinterpret_cast<const float2*>(x + i0);
        float2 xv1 = *reinterpret_cast<const float2*>(x + i1);
        *reinterpret_cast<float2*>(out + i0) = make_float2(acc2[t][0]+xv0.x, acc2[t][1]+xv0.y);
        *reinterpret_cast<float2*>(out + i1) = make_float2(acc2[t][2]+xv1.x, acc2[t][3]+xv1.y);
      }
    }
  }
}

// ============================ l = 1 ============================
struct SL1 {
  float  nw[64];
  __half wp[64][136];
  __half wq[128][72];
  struct HF {
    float  xb[16][196];
    __half A[3][16][72];
    __half H[3][16][136];
    float  ob[16][196];
  } hf[4];
};

DINL void l1_prefetch(SL1::HF& f, const float* x, int n0, int tl){
  #pragma unroll
  for (int i = tl; i < 768; i += 256){
    int row = i/48, q = i - 48*row;
    cpasync16(su32(&f.xb[row][q*4]), x + (size_t)(n0+row)*XDIM + 128 + q*4);
  }
}

__global__ __launch_bounds__(NTHR,1) void k_l1(const float* __restrict__ x,
                                               float* __restrict__ out,
                                               const float* __restrict__ w1){
  extern __shared__ __align__(16) char smem[];
  SL1& s = *reinterpret_cast<SL1*>(smem);
  const int tid = threadIdx.x, lane = tid & 31, warp = tid >> 5;
  const int qg = warp >> 3, wl = warp & 7, tl = tid & 255;
  SL1::HF& f = s.hf[qg];

  for (int i=tid;i<64*128;i+=NTHR) s.wp[i>>7][i&127] = WP1[i];
  for (int i=tid;i<128*64;i+=NTHR) s.wq[i>>6][i&63]  = WQ1[i];
  if (tid < 64) s.nw[tid] = w1[tid];

  const int vc = blockIdx.x*4 + qg;
  l1_prefetch(f, x, vc*16, tl);
  cpcommit();
  __syncthreads();

  const unsigned aB = su32(&f.A[0][0][0]);
  const unsigned hB = su32(&f.H[0][0][0]);
  const unsigned pB = su32(&s.wp[0][0]);
  const unsigned qB = su32(&s.wq[0][0]);
  const int bid = qg + 1;

  const int g1c = wl << 4;           // GEMM1: 8 warps, 16x16, all m
  const int g2c = wl << 4;           // GEMM2: 4 warps (wl<4), 16x16, all m

  for (int tile = vc; tile < NT16; tile += VSTRIDE){
    const int n0 = tile * 16;
    cpwait0();
    barq(bid);
    { // ---- RMS norm from xb -> A[m][n][c] ----
      const int row = tl >> 4, sub = tl & 15;
      const float4* xr = reinterpret_cast<const float4*>(&f.xb[row][sub*12]);
      float4 w[3];
      #pragma unroll
      for (int j=0;j<3;j++) w[j] = xr[j];
      float vv[12] = {w[0].x,w[0].y,w[0].z,w[0].w, w[1].x,w[1].y,w[1].z,w[1].w,
                      w[2].x,w[2].y,w[2].z,w[2].w};
      float sq = 0.f;
      #pragma unroll
      for (int j=0;j<12;j++) sq += vv[j]*vv[j];
      #pragma unroll
      for (int o=1;o<16;o<<=1) sq += __shfl_xor_sync(~0u, sq, o);
      float rinv = rsqrtf(sq*(1.f/64.f) + 1e-5f);
      const int c0 = sub*4;
      float nw0 = s.nw[c0], nw1 = s.nw[c0+1], nw2 = s.nw[c0+2], nw3 = s.nw[c0+3];
      #pragma unroll
      for (int m=0;m<3;m++){
        __half2 p0 = __floats2half2_rn(vv[m]*rinv*nw0,   vv[m+3]*rinv*nw1);
        __half2 p1 = __floats2half2_rn(vv[m+6]*rinv*nw2, vv[m+9]*rinv*nw3);
        *reinterpret_cast<__half2*>(&f.A[m][row][c0])   = p0;
        *reinterpret_cast<__half2*>(&f.A[m][row][c0+2]) = p1;
      }
    }
    barq(bid);
    { // prefetch next tile
      int nt = tile + VSTRIDE;
      if (nt < NT16) l1_prefetch(f, x, nt*16, tl);
      cpcommit();
    }
    { // ---- GEMM1 (m-batched, 8 warps, 16x16) + in-register gate -> H[m][n][o] ----
      float acc[3][2][4];
      #pragma unroll
      for (int m=0;m<3;m++)
        #pragma unroll
        for (int j=0;j<2;j++){ acc[m][j][0]=acc[m][j][1]=acc[m][j][2]=acc[m][j][3]=0.f; }
      #pragma unroll
      for (int k=0;k<4;k++){
        unsigned b0,b1,b2,b3;
        ldmx4t(b0,b1,b2,b3, baddr(pB,136,k*16,g1c,lane));
        #pragma unroll
        for (int m=0;m<3;m++){
          unsigned a0,a1,a2,a3;
          ldmx4(a0,a1,a2,a3, aaddr(aB + m*2304u, 72, 0, k*16, lane));
          mma16816(acc[m][0], a0,a1,a2,a3, b0,b1);
          mma16816(acc[m][1], a0,a1,a2,a3, b2,b3);
        }
      }
      const int rr = lane>>2, ccl = (lane&3)<<1;
      #pragma unroll
      for (int j=0;j<2;j++){
        float g0 = sigm(sqrtf(acc[0][j][0]*acc[0][j][0] + acc[1][j][0]*acc[1][j][0] + acc[2][j][0]*acc[2][j][0] + 1e-12f));
        float g1 = sigm(sqrtf(acc[0][j][1]*acc[0][j][1] + acc[1][j][1]*acc[1][j][1] + acc[2][j][1]*acc[2][j][1] + 1e-12f));
        float g2 = sigm(sqrtf(acc[0][j][2]*acc[0][j][2] + acc[1][j][2]*acc[1][j][2] + acc[2][j][2]*acc[2][j][2] + 1e-12f));
        float g3 = sigm(sqrtf(acc[0][j][3]*acc[0][j][3] + acc[1][j][3]*acc[1][j][3] + acc[2][j][3]*acc[2][j][3] + 1e-12f));
        int c = g1c + 8*j + ccl;
        #pragma unroll
        for (int m=0;m<3;m++){
          *reinterpret_cast<__half2*>(&f.H[m][rr  ][c]) = __floats2half2_rn(acc[m][j][0]*g0, acc[m][j][1]*g1);
          *reinterpret_cast<__half2*>(&f.H[m][rr+8][c]) = __floats2half2_rn(acc[m][j][2]*g2, acc[m][j][3]*g3);
        }
      }
    }
    barq(bid);
    if (wl < 4){ // ---- GEMM2 (m-batched, 4 warps, 16x16) -> ob ----
      float acc2[3][2][4];
      #pragma unroll
      for (int m=0;m<3;m++)
        #pragma unroll
        for (int j=0;j<2;j++){ acc2[m][j][0]=acc2[m][j][1]=acc2[m][j][2]=acc2[m][j][3]=0.f; }
      #pragma unroll
      for (int k=0;k<8;k++){
        unsigned b0,b1,b2,b3;
        ldmx4t(b0,b1,b2,b3, baddr(qB,72,k*16,g2c,lane));
        #pragma unroll
        for (int m=0;m<3;m++){
          unsigned a0,a1,a2,a3;
          ldmx4(a0,a1,a2,a3, aaddr(hB + m*4352u, 136, 0, k*16, lane));
          mma16816(acc2[m][0], a0,a1,a2,a3, b0,b1);
          mma16816(acc2[m][1], a0,a1,a2,a3, b2,b3);
        }
      }
      const int rr = lane>>2, ccl = (lane&3)<<1;
      #pragma unroll
      for (int j=0;j<2;j++){
        int c = g2c + 8*j + ccl;
        #pragma unroll
        for (int hh=0;hh<2;hh++){
          int n = rr + 8*hh;
          #pragma unroll
          for (int m=0;m<3;m++){
            f.ob[n][c*3 + m]     = acc2[m][j][2*hh];
            f.ob[n][(c+1)*3 + m] = acc2[m][j][2*hh+1];
          }
        }
      }
    }
    barq(bid);
    { // ---- coalesced store + residual ----
      #pragma unroll
      for (int i=0;i<3;i++){
        int idx = tl + i*256;          // 16 rows * 48 float4 = 768
        int row = idx/48, q = idx - 48*row;
        float4 v = *reinterpret_cast<const float4*>(&f.ob[row][q*4]);
        const float4 xv = *reinterpret_cast<const float4*>(x + (size_t)(n0+row)*XDIM + 128 + q*4);
        *reinterpret_cast<float4*>(out + (size_t)(n0+row)*XDIM + 128 + q*4) =
          make_float4(v.x+xv.x, v.y+xv.y, v.z+xv.z, v.w+xv.w);
      }
    }
  }
}

// ============================ l = 2 ============================
struct SL2 {
  float  nw[32];
  __half wp[32][72];
  __half wq[64][40];
  struct HF {
    float  xb[16][164];
    __half A[5][16][40];
    __half H[5][16][72];
    float  ob[16][164];
  } hf[4];
};

DINL void l2_prefetch(SL2::HF& f, const float* x, int n0, int tl){
  #pragma unroll
  for (int i = tl; i < 640; i += 256){
    int row = i/40, q = i - 40*row;
    cpasync16(su32(&f.xb[row][q*4]), x + (size_t)(n0+row)*XDIM + 320 + q*4);
  }
}

__global__ __launch_bounds__(NTHR,1) void k_l2(const float* __restrict__ x,
                                               float* __restrict__ out,
                                               const float* __restrict__ w2){
  extern __shared__ __align__(16) char smem[];
  SL2& s = *reinterpret_cast<SL2*>(smem);
  const int tid = threadIdx.x, lane = tid & 31, warp = tid >> 5;
  const int qg = warp >> 3, wl = warp & 7, tl = tid & 255;
  SL2::HF& f = s.hf[qg];

  for (int i=tid;i<32*64;i+=NTHR) s.wp[i>>6][i&63] = WP2[i];
  for (int i=tid;i<64*32;i+=NTHR) s.wq[i>>5][i&31] = WQ2[i];
  if (tid < 32) s.nw[tid] = w2[tid];

  const int vc = blockIdx.x*4 + qg;
  l2_prefetch(f, x, vc*16, tl);
  cpcommit();
  __syncthreads();

  const unsigned aB = su32(&f.A[0][0][0]);
  const unsigned hB = su32(&f.H[0][0][0]);
  const unsigned pB = su32(&s.wp[0][0]);
  const unsigned qB = su32(&s.wq[0][0]);
  const int bid = qg + 1;

  const int g1c = wl << 3;           // GEMM1: 8 warps, 16x8, all m
  const int g2c = wl << 3;           // GEMM2: 4 warps (wl<4), 16x8, all m

  for (int tile = vc; tile < NT16; tile += VSTRIDE){
    const int n0 = tile * 16;
    cpwait0();
    barq(bid);
    { // ---- RMS norm from xb -> A[m][n][c] (half2 stores) ----
      const int row = tl >> 4, sub = tl & 15;
      const float2* xr = reinterpret_cast<const float2*>(&f.xb[row][sub*10]);
      float2 w[5];
      #pragma unroll
      for (int j=0;j<5;j++) w[j] = xr[j];
      float vv[10] = {w[0].x,w[0].y, w[1].x,w[1].y, w[2].x,w[2].y,
                      w[3].x,w[3].y, w[4].x,w[4].y};
      float sq = 0.f;
      #pragma unroll
      for (int j=0;j<10;j++) sq += vv[j]*vv[j];
      #pragma unroll
      for (int o=1;o<16;o<<=1) sq += __shfl_xor_sync(~0u, sq, o);
      float rinv = rsqrtf(sq*(1.f/32.f) + 1e-5f);
      const int c0 = sub*2;
      float nw0 = s.nw[c0], nw1 = s.nw[c0+1];
      #pragma unroll
      for (int m=0;m<5;m++){
        *reinterpret_cast<__half2*>(&f.A[m][row][c0]) =
          __floats2half2_rn(vv[m]*rinv*nw0, vv[m+5]*rinv*nw1);
      }
    }
    barq(bid);
    { // prefetch next tile
      int nt = tile + VSTRIDE;
      if (nt < NT16) l2_prefetch(f, x, nt*16, tl);
      cpcommit();
    }
    { // ---- GEMM1 (m-batched, 8 warps, 16x8) + in-register gate -> H[m][n][o] ----
      float acc[5][4];
      #pragma unroll
      for (int m=0;m<5;m++){ acc[m][0]=acc[m][1]=acc[m][2]=acc[m][3]=0.f; }
      #pragma unroll
      for (int k=0;k<2;k++){
        unsigned b0,b1;
        ldmx2t(b0,b1, b2addr(pB,72,k*16,g1c,lane));
        #pragma unroll
        for (int m=0;m<5;m++){
          unsigned a0,a1,a2,a3;
          ldmx4(a0,a1,a2,a3, aaddr(aB + m*1280u, 40, 0, k*16, lane));
          mma16816(acc[m], a0,a1,a2,a3, b0,b1);
        }
      }
      const int rr = lane>>2;
      const int c  = g1c + ((lane&3)<<1);
      float g0 = sigm(sqrtf(acc[0][0]*acc[0][0]+acc[1][0]*acc[1][0]+acc[2][0]*acc[2][0]+acc[3][0]*acc[3][0]+acc[4][0]*acc[4][0] + 1e-12f));
      float g1 = sigm(sqrtf(acc[0][1]*acc[0][1]+acc[1][1]*acc[1][1]+acc[2][1]*acc[2][1]+acc[3][1]*acc[3][1]+acc[4][1]*acc[4][1] + 1e-12f));
      float g2 = sigm(sqrtf(acc[0][2]*acc[0][2]+acc[1][2]*acc[1][2]+acc[2][2]*acc[2][2]+acc[3][2]*acc[3][2]+acc[4][2]*acc[4][2] + 1e-12f));
      float g3 = sigm(sqrtf(acc[0][3]*acc[0][3]+acc[1][3]*acc[1][3]+acc[2][3]*acc[2][3]+acc[3][3]*acc[3][3]+acc[4][3]*acc[4][3] + 1e-12f));
      #pragma unroll
      for (int m=0;m<5;m++){
        *reinterpret_cast<__half2*>(&f.H[m][rr  ][c]) = __floats2half2_rn(acc[m][0]*g0, acc[m][1]*g1);
        *reinterpret_cast<__half2*>(&f.H[m][rr+8][c]) = __floats2half2_rn(acc[m][2]*g2, acc[m][3]*g3);
      }
    }
    barq(bid);
    if (wl < 4){ // ---- GEMM2 (m-batched, 4 warps, 16x8) -> ob ----
      float acc2[5][4];
      #pragma unroll
      for (int m=0;m<5;m++){ acc2[m][0]=acc2[m][1]=acc2[m][2]=acc2[m][3]=0.f; }
      #pragma unroll
      for (int k=0;k<4;k++){
        unsigned b0,b1;
        ldmx2t(b0,b1, b2addr(qB,40,k*16,g2c,lane));
        #pragma unroll
        for (int m=0;m<5;m++){
          unsigned a0,a1,a2,a3;
          ldmx4(a0,a1,a2,a3, aaddr(hB + m*2304u, 72, 0, k*16, lane));
          mma16816(acc2[m], a0,a1,a2,a3, b0,b1);
        }
      }
      const int rr = lane>>2;
      const int c  = g2c + ((lane&3)<<1);
      #pragma unroll
      for (int hh=0;hh<2;hh++){
        int n = rr + 8*hh;
        #pragma unroll
        for (int m=0;m<5;m++){
          f.ob[n][c*5 + m]     = acc2[m][2*hh];
          f.ob[n][(c+1)*5 + m] = acc2[m][2*hh+1];
        }
      }
    }
    barq(bid);
    { // ---- coalesced store + residual ----
      #pragma unroll
      for (int i=0;i<3;i++){
        int idx = tl + i*256;          // 16 rows * 40 float4 = 640
        if (idx < 640){
          int row = idx/40, q = idx - 40*row;
          float4 v = *reinterpret_cast<const float4*>(&f.ob[row][q*4]);
          const float4 xv = *reinterpret_cast<const float4*>(x + (size_t)(n0+row)*XDIM + 320 + q*4);
          *reinterpret_cast<float4*>(out + (size_t)(n0+row)*XDIM + 320 + q*4) =
            make_float4(v.x+xv.x, v.y+xv.y, v.z+xv.z, v.w+xv.w);
        }
      }
    }
  }
}

extern "C" void kernel_launch(void* const* d_in, const int* in_sizes, int n_in,
                              void* d_out, int out_size){
  const float* x   = (const float*)d_in[0];
  const float* nw0 = (const float*)d_in[1];
  const float* nb0 = (const float*)d_in[2];
  const float* nw1 = (const float*)d_in[3];
  const float* nw2 = (const float*)d_in[4];
  const float* p0  = (const float*)d_in[5];
  const float* p1  = (const float*)d_in[6];
  const float* p2  = (const float*)d_in[7];
  const float* q0  = (const float*)d_in[8];
  const float* q1  = (const float*)d_in[9];
  const float* q2  = (const float*)d_in[10];
  float* out = (float*)d_out;

  cudaFuncSetAttribute(k_l0, cudaFuncAttributeMaxDynamicSharedMemorySize, (int)sizeof(SL0));
  cudaFuncSetAttribute(k_l1, cudaFuncAttributeMaxDynamicSharedMemorySize, (int)sizeof(SL1));
  cudaFuncSetAttribute(k_l2, cudaFuncAttributeMaxDynamicSharedMemorySize, (int)sizeof(SL2));

  k_prep<<<96, 256>>>(p0, p1, p2, q0, q1, q2);
  k_l0<<<GRID, NTHR, sizeof(SL0)>>>(x, out, nw0, nb0);
  k_l1<<<GRID, NTHR, sizeof(SL1)>>>(x, out, nw1);
  k_l2<<<GRID, NTHR, sizeof(SL2)>>>(x, out, nw2);
}